// round 1
// baseline (speedup 1.0000x reference)
#include <cuda_runtime.h>
#include <cuda_bf16.h>
#include <cstdint>

// Problem constants (fixed by the reference: S=64, C=32)
#define SPATIAL 64
#define KEY_SPACE (SPATIAL * SPATIAL * SPATIAL * SPATIAL)  // 16,777,216
#define NWORDS (KEY_SPACE / 32)                            // 524,288
#define NBLOCKS_SCAN 512                                   // NWORDS / 1024
#define CCH 32                                             // channels

// Scratch: presence bitmap over key space, per-word exclusive prefix, block sums
__device__ unsigned g_bitmap[NWORDS];
__device__ unsigned g_wordPrefix[NWORDS];
__device__ unsigned g_blockSums[NBLOCKS_SCAN];

// ---------------------------------------------------------------------------
// 1) zero bitmap
__global__ void k_zero_bitmap() {
    int i = blockIdx.x * blockDim.x + threadIdx.x;  // NWORDS/4 threads, uint4
    ((uint4*)g_bitmap)[i] = make_uint4(0, 0, 0, 0);
}

// 1b) zero output (padding rows must be zero; d_out is poisoned)
__global__ void k_zero_out(float4* out, int n4) {
    int i = blockIdx.x * blockDim.x + threadIdx.x;
    if (i < n4) out[i] = make_float4(0.f, 0.f, 0.f, 0.f);
}

// ---------------------------------------------------------------------------
// 2) build presence bitmap
__global__ void k_build_bitmap(const int4* __restrict__ coords, int n) {
    int i = blockIdx.x * blockDim.x + threadIdx.x;
    if (i >= n) return;
    int4 c = coords[i];
    unsigned key = ((unsigned)((c.x * SPATIAL + c.y) * SPATIAL + c.z)) * SPATIAL + (unsigned)c.w;
    atomicOr(&g_bitmap[key >> 5], 1u << (key & 31));
}

// ---------------------------------------------------------------------------
// 3a) per-block popcount sums (each block covers 1024 words via 256 x uint4)
__global__ void k_block_reduce() {
    int blk = blockIdx.x, t = threadIdx.x;
    uint4 v = ((const uint4*)g_bitmap)[blk * 256 + t];
    unsigned s = __popc(v.x) + __popc(v.y) + __popc(v.z) + __popc(v.w);
#pragma unroll
    for (int o = 16; o; o >>= 1) s += __shfl_down_sync(0xffffffffu, s, o);
    __shared__ unsigned ws[8];
    if ((t & 31) == 0) ws[t >> 5] = s;
    __syncthreads();
    if (t < 8) {
        unsigned x = ws[t];
#pragma unroll
        for (int o = 4; o; o >>= 1) x += __shfl_down_sync(0xffu, x, o);
        if (t == 0) g_blockSums[blk] = x;
    }
}

// 3b) exclusive scan of the 512 block sums (one block, 512 threads)
__global__ void k_scan_sums() {
    int t = threadIdx.x;
    unsigned orig = g_blockSums[t];
    unsigned v = orig;
#pragma unroll
    for (int o = 1; o < 32; o <<= 1) {
        unsigned nv = __shfl_up_sync(0xffffffffu, v, o);
        if ((t & 31) >= o) v += nv;
    }
    __shared__ unsigned wt[16];
    if ((t & 31) == 31) wt[t >> 5] = v;
    __syncthreads();
    if (t < 16) {
        unsigned x = wt[t], xi = x;
#pragma unroll
        for (int o = 1; o < 16; o <<= 1) {
            unsigned nv = __shfl_up_sync(0xffffu, xi, o);
            if (t >= o) xi += nv;
        }
        wt[t] = xi - x;  // exclusive warp offset
    }
    __syncthreads();
    g_blockSums[t] = (v - orig) + wt[t >> 5];  // global exclusive
}

// 3c) per-word exclusive prefix = blockOffset + intra-block exclusive scan
__global__ void k_write_prefix() {
    int blk = blockIdx.x, t = threadIdx.x;
    uint4 v = ((const uint4*)g_bitmap)[blk * 256 + t];
    unsigned c0 = __popc(v.x), c1 = __popc(v.y), c2 = __popc(v.z), c3 = __popc(v.w);
    unsigned local = c0 + c1 + c2 + c3;
    unsigned inc = local;
#pragma unroll
    for (int o = 1; o < 32; o <<= 1) {
        unsigned nv = __shfl_up_sync(0xffffffffu, inc, o);
        if ((t & 31) >= o) inc += nv;
    }
    __shared__ unsigned ws[8];
    if ((t & 31) == 31) ws[t >> 5] = inc;
    __syncthreads();
    if (t < 8) {
        unsigned x = ws[t], xi = x;
#pragma unroll
        for (int o = 1; o < 8; o <<= 1) {
            unsigned nv = __shfl_up_sync(0xffu, xi, o);
            if (t >= o) xi += nv;
        }
        ws[t] = xi - x;
    }
    __syncthreads();
    unsigned excl = (inc - local) + ws[t >> 5] + g_blockSums[blk];
    uint4 outv;
    outv.x = excl;
    outv.y = excl + c0;
    outv.z = outv.y + c1;
    outv.w = outv.z + c2;
    ((uint4*)g_wordPrefix)[blk * 256 + t] = outv;
}

// ---------------------------------------------------------------------------
// 4) scatter-add: 8 threads per point, one red.global.add.v4.f32 each
__global__ void k_scatter(const int4* __restrict__ coords,
                          const float4* __restrict__ feat,
                          float4* __restrict__ out, int n) {
    int tid = blockIdx.x * blockDim.x + threadIdx.x;
    int p = tid >> 3;   // point index
    int q = tid & 7;    // quarter-row index (4 floats each)
    if (p >= n) return;
    int lane = threadIdx.x & 31;
    unsigned rank = 0;
    if (q == 0) {
        int4 c = coords[p];
        unsigned key = ((unsigned)((c.x * SPATIAL + c.y) * SPATIAL + c.z)) * SPATIAL + (unsigned)c.w;
        unsigned w = key >> 5, b = key & 31;
        rank = g_wordPrefix[w] + __popc(g_bitmap[w] & ((1u << b) - 1u));
    }
    rank = __shfl_sync(0xffffffffu, rank, lane & ~7);
    float4 f = feat[p * 8 + q];
    float* dst = (float*)(out + (size_t)rank * 8 + q);
    asm volatile("red.global.add.v4.f32 [%0], {%1,%2,%3,%4};"
                 :: "l"(dst), "f"(f.x), "f"(f.y), "f"(f.z), "f"(f.w)
                 : "memory");
}

// ---------------------------------------------------------------------------
extern "C" void kernel_launch(void* const* d_in, const int* in_sizes, int n_in,
                              void* d_out, int out_size) {
    const int4*   coords = (const int4*)d_in[0];   // [N,4] int32
    const float4* feat   = (const float4*)d_in[1]; // [N,32] f32 viewed as [N,8] float4
    float4*       out    = (float4*)d_out;         // [N,32] f32
    int n = in_sizes[0] / 4;

    // 1) clear scratch + output
    k_zero_bitmap<<<(NWORDS / 4) / 256, 256>>>();
    int n4 = (n * CCH) / 4;  // out_size/4 float4s
    k_zero_out<<<(n4 + 255) / 256, 256>>>(out, n4);

    // 2) presence bitmap
    k_build_bitmap<<<(n + 255) / 256, 256>>>(coords, n);

    // 3) rank prefix
    k_block_reduce<<<NBLOCKS_SCAN, 256>>>();
    k_scan_sums<<<1, NBLOCKS_SCAN>>>();
    k_write_prefix<<<NBLOCKS_SCAN, 256>>>();

    // 4) scatter-add features into unique-rank rows
    int total = n * 8;
    k_scatter<<<(total + 255) / 256, 256>>>(coords, feat, out, n);
}

// round 2
// speedup vs baseline: 1.0756x; 1.0756x over previous
#include <cuda_runtime.h>
#include <cuda_bf16.h>
#include <cstdint>

// Problem constants (fixed by the reference: S=64, C=32)
#define SPATIAL 64
#define KEY_SPACE (SPATIAL * SPATIAL * SPATIAL * SPATIAL)  // 16,777,216
#define NWORDS (KEY_SPACE / 32)                            // 524,288
#define NBLOCKS_SCAN 512                                   // NWORDS / 1024
#define MAXN (1 << 21)                                     // key cache capacity

// Scratch (device globals — no allocation allowed)
__device__ unsigned g_bitmap[NWORDS];      // presence bits
__device__ unsigned g_dup[NWORDS];         // duplicate-key bits (count >= 2)
__device__ unsigned g_wordPrefix[NWORDS];  // exclusive prefix of popcounts
__device__ unsigned g_blockSums[NBLOCKS_SCAN];
__device__ unsigned g_keys[MAXN];          // cached linear keys per point
__device__ unsigned g_numUnique;

// ---------------------------------------------------------------------------
// 1) zero presence + dup bitmaps (4 MB)
__global__ void k_zero_bitmaps() {
    int i = blockIdx.x * blockDim.x + threadIdx.x;  // 2*NWORDS/4 threads
    uint4 z = make_uint4(0, 0, 0, 0);
    if (i < NWORDS / 4) ((uint4*)g_bitmap)[i] = z;
    else                ((uint4*)g_dup)[i - NWORDS / 4] = z;
}

// ---------------------------------------------------------------------------
// 2) build presence bitmap, mark duplicates, cache keys
__global__ void k_build(const int4* __restrict__ coords, int n) {
    int i = blockIdx.x * blockDim.x + threadIdx.x;
    if (i >= n) return;
    int4 c = coords[i];
    unsigned key = ((unsigned)((c.x * SPATIAL + c.y) * SPATIAL + c.z)) * SPATIAL + (unsigned)c.w;
    g_keys[i] = key;
    unsigned bit = 1u << (key & 31);
    unsigned old = atomicOr(&g_bitmap[key >> 5], bit);
    if (old & bit) atomicOr(&g_dup[key >> 5], bit);
}

// ---------------------------------------------------------------------------
// 3a) per-block popcount sums (each block covers 1024 words via 256 x uint4)
__global__ void k_block_reduce() {
    int blk = blockIdx.x, t = threadIdx.x;
    uint4 v = ((const uint4*)g_bitmap)[blk * 256 + t];
    unsigned s = __popc(v.x) + __popc(v.y) + __popc(v.z) + __popc(v.w);
#pragma unroll
    for (int o = 16; o; o >>= 1) s += __shfl_down_sync(0xffffffffu, s, o);
    __shared__ unsigned ws[8];
    if ((t & 31) == 0) ws[t >> 5] = s;
    __syncthreads();
    if (t < 8) {
        unsigned x = ws[t];
#pragma unroll
        for (int o = 4; o; o >>= 1) x += __shfl_down_sync(0xffu, x, o);
        if (t == 0) g_blockSums[blk] = x;
    }
}

// 3b) exclusive scan of the 512 block sums (one block, 512 threads)
__global__ void k_scan_sums() {
    int t = threadIdx.x;
    unsigned orig = g_blockSums[t];
    unsigned v = orig;
#pragma unroll
    for (int o = 1; o < 32; o <<= 1) {
        unsigned nv = __shfl_up_sync(0xffffffffu, v, o);
        if ((t & 31) >= o) v += nv;
    }
    __shared__ unsigned wt[16];
    if ((t & 31) == 31) wt[t >> 5] = v;
    __syncthreads();
    if (t < 16) {
        unsigned x = wt[t], xi = x;
#pragma unroll
        for (int o = 1; o < 16; o <<= 1) {
            unsigned nv = __shfl_up_sync(0xffffu, xi, o);
            if (t >= o) xi += nv;
        }
        wt[t] = xi - x;  // exclusive warp offset
    }
    __syncthreads();
    unsigned excl = (v - orig) + wt[t >> 5];
    g_blockSums[t] = excl;
    if (t == NBLOCKS_SCAN - 1) g_numUnique = excl + orig;  // total uniques
}

// 3c) per-word exclusive prefix = blockOffset + intra-block exclusive scan
__global__ void k_write_prefix() {
    int blk = blockIdx.x, t = threadIdx.x;
    uint4 v = ((const uint4*)g_bitmap)[blk * 256 + t];
    unsigned c0 = __popc(v.x), c1 = __popc(v.y), c2 = __popc(v.z), c3 = __popc(v.w);
    unsigned local = c0 + c1 + c2 + c3;
    unsigned inc = local;
#pragma unroll
    for (int o = 1; o < 32; o <<= 1) {
        unsigned nv = __shfl_up_sync(0xffffffffu, inc, o);
        if ((t & 31) >= o) inc += nv;
    }
    __shared__ unsigned ws[8];
    if ((t & 31) == 31) ws[t >> 5] = inc;
    __syncthreads();
    if (t < 8) {
        unsigned x = ws[t], xi = x;
#pragma unroll
        for (int o = 1; o < 8; o <<= 1) {
            unsigned nv = __shfl_up_sync(0xffu, xi, o);
            if (t >= o) xi += nv;
        }
        ws[t] = xi - x;
    }
    __syncthreads();
    unsigned excl = (inc - local) + ws[t >> 5] + g_blockSums[blk];
    uint4 outv;
    outv.x = excl;
    outv.y = excl + c0;
    outv.z = outv.y + c1;
    outv.w = outv.z + c2;
    ((uint4*)g_wordPrefix)[blk * 256 + t] = outv;
}

// ---------------------------------------------------------------------------
// 4a) zero only duplicate-key rows (they get red.global accumulation)
__global__ void k_dup_zero(float4* __restrict__ out) {
    int w = blockIdx.x * blockDim.x + threadIdx.x;  // one thread per word
    if (w >= NWORDS) return;
    unsigned d = g_dup[w];
    if (!d) return;
    unsigned present = g_bitmap[w], pref = g_wordPrefix[w];
    float4 z = make_float4(0.f, 0.f, 0.f, 0.f);
    while (d) {
        int b = __ffs(d) - 1;
        d &= d - 1;
        unsigned rank = pref + __popc(present & ((1u << b) - 1u));
        float4* dst = out + (size_t)rank * 8;
#pragma unroll
        for (int q = 0; q < 8; q++) dst[q] = z;
    }
}

// 4b) zero padding rows (rank >= numUnique) — output is poisoned
__global__ void k_pad_zero(float4* __restrict__ out, int n) {
    int tid = blockIdx.x * blockDim.x + threadIdx.x;
    int row = tid >> 3;
    if (row >= n) return;
    if ((unsigned)row >= g_numUnique)
        out[(size_t)row * 8 + (tid & 7)] = make_float4(0.f, 0.f, 0.f, 0.f);
}

// ---------------------------------------------------------------------------
// 5) scatter: singleton keys use plain ST.128 (no RMW); dup keys use RED
__global__ void k_scatter(const float4* __restrict__ feat,
                          float4* __restrict__ out, int n) {
    int tid = blockIdx.x * blockDim.x + threadIdx.x;
    int p = tid >> 3;   // point index
    int q = tid & 7;    // quarter-row index (4 floats)
    if (p >= n) return;
    int lane = threadIdx.x & 31;
    unsigned info = 0;
    if (q == 0) {
        unsigned key = g_keys[p];
        unsigned w = key >> 5, b = key & 31;
        unsigned rank = g_wordPrefix[w] + __popc(g_bitmap[w] & ((1u << b) - 1u));
        unsigned isdup = (g_dup[w] >> b) & 1u;
        info = rank | (isdup << 31);
    }
    info = __shfl_sync(0xffffffffu, info, lane & ~7);
    unsigned rank = info & 0x7fffffffu;
    float4 f = feat[p * 8 + q];
    float4* dst = out + (size_t)rank * 8 + q;
    if (info >> 31) {
        asm volatile("red.global.add.v4.f32 [%0], {%1,%2,%3,%4};"
                     :: "l"((float*)dst), "f"(f.x), "f"(f.y), "f"(f.z), "f"(f.w)
                     : "memory");
    } else {
        *dst = f;  // full 128B row covered by the 8 sibling threads — no zero needed
    }
}

// ---------------------------------------------------------------------------
extern "C" void kernel_launch(void* const* d_in, const int* in_sizes, int n_in,
                              void* d_out, int out_size) {
    const int4*   coords = (const int4*)d_in[0];   // [N,4] int32
    const float4* feat   = (const float4*)d_in[1]; // [N,32] f32 as [N,8] float4
    float4*       out    = (float4*)d_out;         // [N,32] f32
    int n = in_sizes[0] / 4;

    // 1) clear bitmaps
    k_zero_bitmaps<<<(2 * NWORDS / 4) / 256, 256>>>();

    // 2) presence + duplicate bitmaps, key cache
    k_build<<<(n + 255) / 256, 256>>>(coords, n);

    // 3) rank prefix
    k_block_reduce<<<NBLOCKS_SCAN, 256>>>();
    k_scan_sums<<<1, NBLOCKS_SCAN>>>();
    k_write_prefix<<<NBLOCKS_SCAN, 256>>>();

    // 4) zero only what needs zeroing
    k_dup_zero<<<NWORDS / 256, 256>>>(out);
    k_pad_zero<<<(n * 8 + 255) / 256, 256>>>(out, n);

    // 5) scatter
    k_scatter<<<(n * 8 + 255) / 256, 256>>>(feat, out, n);
}

// round 3
// speedup vs baseline: 1.4035x; 1.3049x over previous
#include <cuda_runtime.h>
#include <cuda_bf16.h>
#include <cstdint>

// Problem constants (fixed by the reference: S=64, C=32)
#define SPATIAL 64
#define KEY_SPACE (SPATIAL * SPATIAL * SPATIAL * SPATIAL)  // 16,777,216
#define NWORDS (KEY_SPACE / 32)                            // 524,288
#define NBLOCKS_SCAN 512                                   // NWORDS / 1024
#define MAXN (1 << 21)

// Scratch (device globals — no allocation allowed)
__device__ unsigned g_bitmap[NWORDS];      // presence bits
__device__ unsigned g_dup[NWORDS];         // duplicate-key bits
__device__ unsigned g_wordPrefix[NWORDS];  // exclusive prefix of popcounts
__device__ unsigned long long g_scanState[NBLOCKS_SCAN];  // (sum<<32)|flag; 1=partial,2=inclusive
__device__ unsigned g_keys[MAXN];
__device__ unsigned g_numUnique;

// ---------------------------------------------------------------------------
// 1) zero bitmaps + lookback state
__global__ void k_init() {
    int i = blockIdx.x * blockDim.x + threadIdx.x;
    uint4 z = make_uint4(0, 0, 0, 0);
    if (i < NWORDS / 4)                ((uint4*)g_bitmap)[i] = z;
    else if (i < 2 * (NWORDS / 4))     ((uint4*)g_dup)[i - NWORDS / 4] = z;
    else if (i < 2 * (NWORDS / 4) + NBLOCKS_SCAN / 2)
        ((uint4*)g_scanState)[i - 2 * (NWORDS / 4)] = z;
}

// ---------------------------------------------------------------------------
// 2) presence + dup bitmaps, key cache
__global__ void k_build(const int4* __restrict__ coords, int n) {
    int i = blockIdx.x * blockDim.x + threadIdx.x;
    if (i >= n) return;
    int4 c = coords[i];
    unsigned key = ((unsigned)((c.x * SPATIAL + c.y) * SPATIAL + c.z)) * SPATIAL + (unsigned)c.w;
    g_keys[i] = key;
    unsigned bit = 1u << (key & 31);
    unsigned old = atomicOr(&g_bitmap[key >> 5], bit);
    if (old & bit) atomicOr(&g_dup[key >> 5], bit);
}

// ---------------------------------------------------------------------------
// 3) single-pass scan (decoupled lookback) + inline dup-row zeroing.
//    512 blocks x 256 threads; each thread owns 4 words (uint4).
__global__ void __launch_bounds__(256) k_scan_fused(float4* __restrict__ out) {
    int blk = blockIdx.x, t = threadIdx.x;
    uint4 v = ((const uint4*)g_bitmap)[blk * 256 + t];
    unsigned c0 = __popc(v.x), c1 = __popc(v.y), c2 = __popc(v.z), c3 = __popc(v.w);
    unsigned local = c0 + c1 + c2 + c3;

    // intra-warp inclusive scan
    unsigned inc = local;
#pragma unroll
    for (int o = 1; o < 32; o <<= 1) {
        unsigned nv = __shfl_up_sync(0xffffffffu, inc, o);
        if ((t & 31) >= o) inc += nv;
    }
    __shared__ unsigned ws[8];       // warp totals -> warp exclusive offsets
    __shared__ unsigned sh_total, sh_excl;
    if ((t & 31) == 31) ws[t >> 5] = inc;
    __syncthreads();
    if (t < 8) {
        unsigned x = ws[t], xi = x;
#pragma unroll
        for (int o = 1; o < 8; o <<= 1) {
            unsigned nv = __shfl_up_sync(0xffu, xi, o);
            if (t >= o) xi += nv;
        }
        ws[t] = xi - x;                       // exclusive warp offset
        if (t == 7) sh_total = xi;            // block total
    }
    __syncthreads();
    unsigned blockTotal = sh_total;

    // publish partial, then lookback (warp 0)
    if (t == 0)
        atomicExch(&g_scanState[blk], ((unsigned long long)blockTotal << 32) | 1ULL);
    if (t < 32) {
        unsigned excl = 0;
        int idx = blk - 1;
        while (idx >= 0) {
            int look = idx - t;
            unsigned long long s;
            unsigned flag;
            do {
                s = (look >= 0) ? *(volatile unsigned long long*)&g_scanState[look]
                                : 0x100000000ULL * 0 + 3ULL;  // OOR: flag=3, val=0
                flag = (unsigned)s;
            } while (__any_sync(0xffffffffu, flag == 0));
            unsigned val = (unsigned)(s >> 32);
            unsigned inclMask = __ballot_sync(0xffffffffu, look >= 0 && flag == 2);
            unsigned contrib;
            if (inclMask) {
                int fi = __ffs(inclMask) - 1;  // closest inclusive predecessor
                contrib = (t <= (unsigned)fi && look >= 0) ? val : 0;
            } else {
                contrib = (look >= 0) ? val : 0;
            }
#pragma unroll
            for (int o = 16; o; o >>= 1) contrib += __shfl_down_sync(0xffffffffu, contrib, o);
            excl += __shfl_sync(0xffffffffu, contrib, 0);
            if (inclMask) break;
            idx -= 32;
        }
        if (t == 0) {
            atomicExch(&g_scanState[blk],
                       ((unsigned long long)(excl + blockTotal) << 32) | 2ULL);
            sh_excl = excl;
            if (blk == NBLOCKS_SCAN - 1) g_numUnique = excl + blockTotal;
        }
    }
    __syncthreads();

    unsigned base = sh_excl + ws[t >> 5] + (inc - local);
    uint4 outv;
    outv.x = base;
    outv.y = base + c0;
    outv.z = outv.y + c1;
    outv.w = outv.z + c2;
    ((uint4*)g_wordPrefix)[blk * 256 + t] = outv;

    // inline dup-row zeroing (this thread owns words 4w..4w+3 with known prefixes)
    uint4 d4 = ((const uint4*)g_dup)[blk * 256 + t];
    unsigned dw[4] = {d4.x, d4.y, d4.z, d4.w};
    unsigned pw[4] = {v.x, v.y, v.z, v.w};
    unsigned bw[4] = {outv.x, outv.y, outv.z, outv.w};
    float4 z = make_float4(0.f, 0.f, 0.f, 0.f);
#pragma unroll
    for (int k = 0; k < 4; k++) {
        unsigned d = dw[k];
        while (d) {
            int b = __ffs(d) - 1;
            d &= d - 1;
            unsigned rank = bw[k] + __popc(pw[k] & ((1u << b) - 1u));
            float4* dst = out + (size_t)rank * 8;
#pragma unroll
            for (int q = 0; q < 8; q++) dst[q] = z;
        }
    }
}

// ---------------------------------------------------------------------------
// 4) scatter (singleton ST / dup RED) + padding-row zero (disjoint range)
__global__ void k_scatter(const float4* __restrict__ feat,
                          float4* __restrict__ out, int n) {
    int tid = blockIdx.x * blockDim.x + threadIdx.x;
    int p = tid >> 3;   // point index
    int q = tid & 7;    // quarter-row index
    if (p >= n) return;
    int lane = threadIdx.x & 31;
    unsigned info = 0;
    if (q == 0) {
        unsigned key = g_keys[p];
        unsigned w = key >> 5, b = key & 31;
        unsigned rank = g_wordPrefix[w] + __popc(g_bitmap[w] & ((1u << b) - 1u));
        unsigned isdup = (g_dup[w] >> b) & 1u;
        info = rank | (isdup << 31);
    }
    info = __shfl_sync(0xffffffffu, info, lane & ~7);
    unsigned rank = info & 0x7fffffffu;
    float4 f = feat[p * 8 + q];
    float4* dst = out + (size_t)rank * 8 + q;
    if (info >> 31) {
        asm volatile("red.global.add.v4.f32 [%0], {%1,%2,%3,%4};"
                     :: "l"((float*)dst), "f"(f.x), "f"(f.y), "f"(f.z), "f"(f.w)
                     : "memory");
    } else {
        *dst = f;
    }

    // padding rows [numUnique, n): never touched by scatter, safe to zero here
    unsigned nu = g_numUnique;
    unsigned row = nu + (unsigned)p;
    if (row < (unsigned)n)
        out[(size_t)row * 8 + q] = make_float4(0.f, 0.f, 0.f, 0.f);
}

// ---------------------------------------------------------------------------
extern "C" void kernel_launch(void* const* d_in, const int* in_sizes, int n_in,
                              void* d_out, int out_size) {
    const int4*   coords = (const int4*)d_in[0];
    const float4* feat   = (const float4*)d_in[1];
    float4*       out    = (float4*)d_out;
    int n = in_sizes[0] / 4;

    int initThreads = 2 * (NWORDS / 4) + NBLOCKS_SCAN / 2;
    k_init<<<(initThreads + 255) / 256, 256>>>();
    k_build<<<(n + 255) / 256, 256>>>(coords, n);
    k_scan_fused<<<NBLOCKS_SCAN, 256>>>(out);
    k_scatter<<<(n * 8 + 255) / 256, 256>>>(feat, out, n);
}